// round 12
// baseline (speedup 1.0000x reference)
#include <cuda_runtime.h>
#include <cuda_fp16.h>
#include <cstdint>

// ============================================================================
// Problem dims
// ============================================================================
#define M_TOTAL 8192      // B*S
#define N_TOTAL 4096      // D_out
#define K_TOTAL 4096      // D_in
#define LORA_RANK 32
#define LORA_SCALE (1.0f / 32.0f)

// GEMM tiling: CTA 128x256, 256 threads (8 warps, 2x4), warp tile 64x64.
// 1 CTA/SM -> 255-reg budget AND 2 warps/SMSP. 4-stage cp.async pipeline.
#define BM 128
#define BN 256
#define BK 64                            // halves per stage row (128B)
#define STAGES 4
#define K_ITERS (K_TOTAL / BK)           // 64
#define PAD_H 72                         // halves per smem row (144B, conflict-free rotation)
#define A_ST_HALVES (BM * PAD_H)         // 9216
#define B_ST_HALVES (BN * PAD_H)         // 18432
#define STAGE_HALVES (A_ST_HALVES + B_ST_HALVES)   // 27648
#define SMEM_BYTES (STAGES * STAGE_HALVES * 2)     // 221184 (1 CTA/SM)

// Fused prep grid split
#define O_TILE 32
#define WEFF_BLOCKS (N_TOTAL / O_TILE)                        // 128 (scheduled first)
#define CONV_BLOCKS ((M_TOTAL * K_TOTAL / 8) / 256)           // 16384

// fp16 operand scratch (device globals: allocation-free scratch)
__device__ __half g_Xh[(size_t)M_TOTAL * K_TOTAL];  // [M, K] row-major
__device__ __half g_Wh[(size_t)N_TOTAL * K_TOTAL];  // [N, K] row-major (Weff)

// ============================================================================
// Helpers
// ============================================================================
__device__ __forceinline__ uint32_t smem_u32(const void* p) {
    uint32_t a;
    asm("{ .reg .u64 t; cvta.to.shared.u64 t, %1; cvt.u32.u64 %0, t; }" : "=r"(a) : "l"(p));
    return a;
}

__device__ __forceinline__ void cp_async16(uint32_t smem_dst, const void* gmem_src) {
    asm volatile("cp.async.cg.shared.global [%0], [%1], 16;" :: "r"(smem_dst), "l"(gmem_src));
}
__device__ __forceinline__ void cp_commit() {
    asm volatile("cp.async.commit_group;" ::: "memory");
}
template <int N>
__device__ __forceinline__ void cp_wait() {
    asm volatile("cp.async.wait_group %0;" :: "n"(N) : "memory");
}

__device__ __forceinline__ void ldsm_x4(uint32_t& r0, uint32_t& r1, uint32_t& r2, uint32_t& r3,
                                        uint32_t addr) {
    asm volatile("ldmatrix.sync.aligned.m8n8.x4.shared.b16 {%0,%1,%2,%3}, [%4];"
                 : "=r"(r0), "=r"(r1), "=r"(r2), "=r"(r3) : "r"(addr));
}

__device__ __forceinline__ void mma_f16(float& d0, float& d1, float& d2, float& d3,
                                        uint32_t a0, uint32_t a1, uint32_t a2, uint32_t a3,
                                        uint32_t b0, uint32_t b1) {
    asm volatile(
        "mma.sync.aligned.m16n8k16.row.col.f32.f16.f16.f32 "
        "{%0,%1,%2,%3}, {%4,%5,%6,%7}, {%8,%9}, {%0,%1,%2,%3};"
        : "+f"(d0), "+f"(d1), "+f"(d2), "+f"(d3)
        : "r"(a0), "r"(a1), "r"(a2), "r"(a3), "r"(b0), "r"(b1));
}

// ============================================================================
// Fused prep kernel: blocks [0, WEFF_BLOCKS) build Weff (FMA/L2-bound),
// blocks [WEFF_BLOCKS, ...) convert x -> fp16 (DRAM-bound). Overlapped phases.
// ============================================================================
__global__ __launch_bounds__(256) void prep_kernel(const float* __restrict__ x,
                                                   const float* __restrict__ W,
                                                   const float* __restrict__ A,
                                                   const float* __restrict__ B) {
    __shared__ float Bs[O_TILE][LORA_RANK];   // weff branch only (4KB)

    if (blockIdx.x < WEFF_BLOCKS) {
        const int o0 = blockIdx.x * O_TILE;

        for (int idx = threadIdx.x; idx < O_TILE * LORA_RANK; idx += 256) {
            int r = idx >> 5;
            int o = idx & 31;
            Bs[o][r] = B[(size_t)r * N_TOTAL + o0 + o];   // coalesced over o
        }
        __syncthreads();

#pragma unroll 1
        for (int it = 0; it < K_TOTAL / 256; it++) {
            const int d = it * 256 + threadIdx.x;
            float4 a4[LORA_RANK / 4];
            const float4* arow = reinterpret_cast<const float4*>(A + (size_t)d * LORA_RANK);
#pragma unroll
            for (int j = 0; j < LORA_RANK / 4; j++) a4[j] = arow[j];

#pragma unroll 4
            for (int o = 0; o < O_TILE; o++) {
                const float4* b4 = reinterpret_cast<const float4*>(Bs[o]);  // warp-broadcast
                float acc = 0.0f;
#pragma unroll
                for (int j = 0; j < LORA_RANK / 4; j++) {
                    float4 b = b4[j];
                    acc += a4[j].x * b.x + a4[j].y * b.y + a4[j].z * b.z + a4[j].w * b.w;
                }
                const size_t oi = (size_t)(o0 + o) * K_TOTAL + d;   // coalesced over d
                g_Wh[oi] = __float2half_rn(W[oi] + LORA_SCALE * acc);
            }
        }
    } else {
        size_t i = (size_t)(blockIdx.x - WEFF_BLOCKS) * 256 + threadIdx.x;
        float4 v0 = reinterpret_cast<const float4*>(x)[2 * i];
        float4 v1 = reinterpret_cast<const float4*>(x)[2 * i + 1];
        __half2 h[4];
        h[0] = __floats2half2_rn(v0.x, v0.y);
        h[1] = __floats2half2_rn(v0.z, v0.w);
        h[2] = __floats2half2_rn(v1.x, v1.y);
        h[3] = __floats2half2_rn(v1.z, v1.w);
        reinterpret_cast<uint4*>(g_Xh)[i] = *reinterpret_cast<uint4*>(h);
    }
}

// ============================================================================
// Main GEMM: y = Xh @ Wh^T + bias
// 256 threads, 8 warps (2M x 4N), warp tile 64x64, m16n8k16 fp16, ldmatrix.
// ============================================================================
__global__ __launch_bounds__(256, 1)
void gemm_kernel(const __half* __restrict__ Xh, const __half* __restrict__ Wh,
                 const float* __restrict__ bias, float* __restrict__ out) {
    extern __shared__ __align__(16) __half smem[];

    const int tid = threadIdx.x;
    const int wid = tid >> 5;
    const int lane = tid & 31;
    const int g = lane >> 2;     // group (0..7)
    const int q = lane & 3;      // quad lane (0..3)

    const int warp_m = wid & 1;  // 0..1
    const int warp_n = wid >> 1; // 0..3

    const int n_tiles = N_TOTAL / BN;  // 16
    const int mt = blockIdx.x / n_tiles;
    const int nt = blockIdx.x % n_tiles;
    const int m0 = mt * BM;
    const int n0 = nt * BN;

    const __half* Ag = Xh + (size_t)m0 * K_TOTAL;
    const __half* Bg = Wh + (size_t)n0 * K_TOTAL;

    const uint32_t s_base = smem_u32(smem);

    // Accumulators: 4 m-subtiles x 8 n-subtiles x 4 regs = 128 regs
    float d[4][8][4];
#pragma unroll
    for (int i = 0; i < 4; i++)
#pragma unroll
        for (int j = 0; j < 8; j++) {
            d[i][j][0] = 0.f; d[i][j][1] = 0.f; d[i][j][2] = 0.f; d[i][j][3] = 0.f;
        }

    // ---- Stage loader: A 1024 + B 2048 16B chunks (row = idx/8, ch = idx%8) ----
    auto load_stage = [&](int kt, int slot) {
        const __half* Asrc = Ag + kt * BK;
        const __half* Bsrc = Bg + kt * BK;
        uint32_t sa = s_base + (uint32_t)(slot * STAGE_HALVES) * 2u;
        uint32_t sbb = sa + A_ST_HALVES * 2u;
#pragma unroll
        for (int i = 0; i < 4; i++) {          // A: 128 rows x 8 chunks
            int idx = tid + 256 * i;
            int row = idx >> 3;
            int ch = idx & 7;
            cp_async16(sa + (uint32_t)(row * PAD_H + ch * 8) * 2u,
                       Asrc + (size_t)row * K_TOTAL + ch * 8);
        }
#pragma unroll
        for (int i = 0; i < 8; i++) {          // B: 256 rows x 8 chunks
            int idx = tid + 256 * i;
            int row = idx >> 3;
            int ch = idx & 7;
            cp_async16(sbb + (uint32_t)(row * PAD_H + ch * 8) * 2u,
                       Bsrc + (size_t)row * K_TOTAL + ch * 8);
        }
        cp_commit();
    };

#pragma unroll
    for (int s = 0; s < STAGES - 1; s++) load_stage(s, s);

    const int Am_base = warp_m * 64;
    const int Bn_base = warp_n * 64;

    // ldmatrix per-lane coordinates.
    const int l8 = lane & 7;
    const int aRow = ((lane >> 3) & 1) * 8 + l8;   // + Am_base + tm*16
    const int aK = (lane >> 4) * 8;                // 0 or 8
    const int bRow = (lane >> 4) * 8 + l8;         // + Bn_base + tp*16
    const int bK = ((lane >> 3) & 1) * 8;

    uint32_t aOff[4], bOff[4];
#pragma unroll
    for (int tm = 0; tm < 4; tm++)
        aOff[tm] = (uint32_t)(((Am_base + tm * 16 + aRow) * PAD_H + aK) * 2);
#pragma unroll
    for (int tp = 0; tp < 4; tp++)
        bOff[tp] = (uint32_t)(((Bn_base + tp * 16 + bRow) * PAD_H + bK) * 2 +
                              A_ST_HALVES * 2);

#pragma unroll 1
    for (int kt = 0; kt < K_ITERS; kt++) {
        cp_wait<STAGES - 2>();
        // Single barrier per iteration: after it, stage kt data is visible AND all
        // warps are done reading the slot overwritten below ((kt+3)%4, read at kt-1).
        __syncthreads();

        if (kt + STAGES - 1 < K_ITERS)
            load_stage(kt + STAGES - 1, (kt + STAGES - 1) % STAGES);

        const uint32_t st = s_base + (uint32_t)((kt % STAGES) * STAGE_HALVES) * 2u;

#pragma unroll
        for (int kk = 0; kk < BK; kk += 16) {
            uint32_t a[4][4], b[4][4];
#pragma unroll
            for (int tm = 0; tm < 4; tm++)
                ldsm_x4(a[tm][0], a[tm][1], a[tm][2], a[tm][3], st + aOff[tm] + kk * 2);
#pragma unroll
            for (int tp = 0; tp < 4; tp++)
                ldsm_x4(b[tp][0], b[tp][1], b[tp][2], b[tp][3], st + bOff[tp] + kk * 2);
#pragma unroll
            for (int tm = 0; tm < 4; tm++)
#pragma unroll
                for (int tn = 0; tn < 8; tn++)
                    mma_f16(d[tm][tn][0], d[tm][tn][1], d[tm][tn][2], d[tm][tn][3],
                            a[tm][0], a[tm][1], a[tm][2], a[tm][3],
                            b[tn >> 1][2 * (tn & 1)], b[tn >> 1][2 * (tn & 1) + 1]);
        }
    }

    // ---- Epilogue: d + bias -> gmem ----
#pragma unroll
    for (int tn = 0; tn < 8; tn++) {
        int col = n0 + Bn_base + tn * 8 + 2 * q;
        float2 bb = *reinterpret_cast<const float2*>(bias + col);
#pragma unroll
        for (int tm = 0; tm < 4; tm++) {
            int row0 = m0 + Am_base + tm * 16 + g;
            float2 v0 = make_float2(d[tm][tn][0] + bb.x, d[tm][tn][1] + bb.y);
            float2 v1 = make_float2(d[tm][tn][2] + bb.x, d[tm][tn][3] + bb.y);
            *reinterpret_cast<float2*>(out + (size_t)row0 * N_TOTAL + col) = v0;
            *reinterpret_cast<float2*>(out + (size_t)(row0 + 8) * N_TOTAL + col) = v1;
        }
    }
}

// ============================================================================
// Host launch
// ============================================================================
extern "C" void kernel_launch(void* const* d_in, const int* in_sizes, int n_in,
                              void* d_out, int out_size) {
    const float* x    = (const float*)d_in[0];  // [4,2048,4096]
    const float* W    = (const float*)d_in[1];  // [4096,4096] (out,in)
    const float* bias = (const float*)d_in[2];  // [4096]
    const float* A    = (const float*)d_in[3];  // [4096,32]
    const float* B    = (const float*)d_in[4];  // [32,4096]
    float* y          = (float*)d_out;          // [4,2048,4096]

    void* xh_ptr = nullptr;
    void* wh_ptr = nullptr;
    cudaGetSymbolAddress(&xh_ptr, g_Xh);
    cudaGetSymbolAddress(&wh_ptr, g_Wh);

    // 1) fused prep: weff blocks first (overlap FMA-bound weff with DRAM-bound conversion)
    prep_kernel<<<WEFF_BLOCKS + CONV_BLOCKS, 256>>>(x, W, A, B);
    // 2) main GEMM + bias epilogue
    cudaFuncSetAttribute((const void*)gemm_kernel,
                         cudaFuncAttributeMaxDynamicSharedMemorySize, SMEM_BYTES);
    gemm_kernel<<<(M_TOTAL / BM) * (N_TOTAL / BN), 256, SMEM_BYTES>>>(
        (const __half*)xh_ptr, (const __half*)wh_ptr, bias, y);
}

// round 14
// speedup vs baseline: 1.2546x; 1.2546x over previous
#include <cuda_runtime.h>
#include <cuda_fp16.h>
#include <cstdint>

// ============================================================================
// Problem dims
// ============================================================================
#define M_TOTAL 8192      // B*S
#define N_TOTAL 4096      // D_out
#define K_TOTAL 4096      // D_in
#define LORA_RANK 32
#define LORA_SCALE (1.0f / 32.0f)

// GEMM tiling: R7 shape (best measured) + interleaved cp.async loader.
// CTA 128x128, 256 threads (8 warps, 2x4), warp tile 64x32, 2 CTAs/SM.
#define BM 128
#define BN 128
#define BK 64                            // halves per stage row (128B)
#define STAGES 3
#define K_ITERS (K_TOTAL / BK)           // 64
#define PAD_H 72                         // halves per smem row (144B, conflict-free rotation)
#define A_ST_HALVES (BM * PAD_H)         // 9216
#define B_ST_HALVES (BN * PAD_H)
#define STAGE_HALVES (A_ST_HALVES + B_ST_HALVES)
#define SMEM_BYTES (STAGES * STAGE_HALVES * 2)   // 110592 (2 CTAs/SM)

// Fused prep grid split
#define O_TILE 32
#define WEFF_BLOCKS (N_TOTAL / O_TILE)                        // 128 (scheduled first)
#define CONV_BLOCKS ((M_TOTAL * K_TOTAL / 8) / 256)           // 16384

// fp16 operand scratch (device globals: allocation-free scratch)
__device__ __half g_Xh[(size_t)M_TOTAL * K_TOTAL];  // [M, K] row-major
__device__ __half g_Wh[(size_t)N_TOTAL * K_TOTAL];  // [N, K] row-major (Weff)

// ============================================================================
// Helpers
// ============================================================================
__device__ __forceinline__ uint32_t smem_u32(const void* p) {
    uint32_t a;
    asm("{ .reg .u64 t; cvta.to.shared.u64 t, %1; cvt.u32.u64 %0, t; }" : "=r"(a) : "l"(p));
    return a;
}

__device__ __forceinline__ void cp_async16(uint32_t smem_dst, const void* gmem_src) {
    asm volatile("cp.async.cg.shared.global [%0], [%1], 16;" :: "r"(smem_dst), "l"(gmem_src));
}
__device__ __forceinline__ void cp_commit() {
    asm volatile("cp.async.commit_group;" ::: "memory");
}
template <int N>
__device__ __forceinline__ void cp_wait() {
    asm volatile("cp.async.wait_group %0;" :: "n"(N) : "memory");
}

__device__ __forceinline__ void ldsm_x4(uint32_t& r0, uint32_t& r1, uint32_t& r2, uint32_t& r3,
                                        uint32_t addr) {
    asm volatile("ldmatrix.sync.aligned.m8n8.x4.shared.b16 {%0,%1,%2,%3}, [%4];"
                 : "=r"(r0), "=r"(r1), "=r"(r2), "=r"(r3) : "r"(addr));
}

__device__ __forceinline__ void mma_f16(float& d0, float& d1, float& d2, float& d3,
                                        uint32_t a0, uint32_t a1, uint32_t a2, uint32_t a3,
                                        uint32_t b0, uint32_t b1) {
    asm volatile(
        "mma.sync.aligned.m16n8k16.row.col.f32.f16.f16.f32 "
        "{%0,%1,%2,%3}, {%4,%5,%6,%7}, {%8,%9}, {%0,%1,%2,%3};"
        : "+f"(d0), "+f"(d1), "+f"(d2), "+f"(d3)
        : "r"(a0), "r"(a1), "r"(a2), "r"(a3), "r"(b0), "r"(b1));
}

// ============================================================================
// Fused prep kernel: blocks [0, WEFF_BLOCKS) build Weff (FMA/L2-bound),
// blocks [WEFF_BLOCKS, ...) convert x -> fp16 (DRAM-bound). Overlapped phases.
// ============================================================================
__global__ __launch_bounds__(256) void prep_kernel(const float* __restrict__ x,
                                                   const float* __restrict__ W,
                                                   const float* __restrict__ A,
                                                   const float* __restrict__ B) {
    __shared__ float Bs[O_TILE][LORA_RANK];   // weff branch only (4KB)

    if (blockIdx.x < WEFF_BLOCKS) {
        const int o0 = blockIdx.x * O_TILE;

        for (int idx = threadIdx.x; idx < O_TILE * LORA_RANK; idx += 256) {
            int r = idx >> 5;
            int o = idx & 31;
            Bs[o][r] = B[(size_t)r * N_TOTAL + o0 + o];   // coalesced over o
        }
        __syncthreads();

#pragma unroll 1
        for (int it = 0; it < K_TOTAL / 256; it++) {
            const int d = it * 256 + threadIdx.x;
            float4 a4[LORA_RANK / 4];
            const float4* arow = reinterpret_cast<const float4*>(A + (size_t)d * LORA_RANK);
#pragma unroll
            for (int j = 0; j < LORA_RANK / 4; j++) a4[j] = arow[j];

#pragma unroll 4
            for (int o = 0; o < O_TILE; o++) {
                const float4* b4 = reinterpret_cast<const float4*>(Bs[o]);  // warp-broadcast
                float acc = 0.0f;
#pragma unroll
                for (int j = 0; j < LORA_RANK / 4; j++) {
                    float4 b = b4[j];
                    acc += a4[j].x * b.x + a4[j].y * b.y + a4[j].z * b.z + a4[j].w * b.w;
                }
                const size_t oi = (size_t)(o0 + o) * K_TOTAL + d;   // coalesced over d
                g_Wh[oi] = __float2half_rn(W[oi] + LORA_SCALE * acc);
            }
        }
    } else {
        size_t i = (size_t)(blockIdx.x - WEFF_BLOCKS) * 256 + threadIdx.x;
        float4 v0 = reinterpret_cast<const float4*>(x)[2 * i];
        float4 v1 = reinterpret_cast<const float4*>(x)[2 * i + 1];
        __half2 h[4];
        h[0] = __floats2half2_rn(v0.x, v0.y);
        h[1] = __floats2half2_rn(v0.z, v0.w);
        h[2] = __floats2half2_rn(v1.x, v1.y);
        h[3] = __floats2half2_rn(v1.z, v1.w);
        reinterpret_cast<uint4*>(g_Xh)[i] = *reinterpret_cast<uint4*>(h);
    }
}

// ============================================================================
// Main GEMM: y = Xh @ Wh^T + bias
// 256 threads, 8 warps (2M x 4N), warp tile 64x32, m16n8k16 fp16, ldmatrix.
// cp.async for stage kt+2 is interleaved INSIDE the kk loop (2 chunks per kk,
// issued between the kk's ldsm and its HMMAs) so fragment loads are never
// queued behind a 8-op cp.async burst at the kt boundary.
// ============================================================================
__global__ __launch_bounds__(256, 2)
void gemm_kernel(const __half* __restrict__ Xh, const __half* __restrict__ Wh,
                 const float* __restrict__ bias, float* __restrict__ out) {
    extern __shared__ __align__(16) __half smem[];

    const int tid = threadIdx.x;
    const int wid = tid >> 5;
    const int lane = tid & 31;
    const int g = lane >> 2;     // group (0..7)
    const int q = lane & 3;      // quad lane (0..3)

    const int warp_m = wid & 1;  // 0..1
    const int warp_n = wid >> 1; // 0..3

    const int n_tiles = N_TOTAL / BN;  // 32
    const int mt = blockIdx.x / n_tiles;
    const int nt = blockIdx.x % n_tiles;
    const int m0 = mt * BM;
    const int n0 = nt * BN;

    const __half* Ag = Xh + (size_t)m0 * K_TOTAL;
    const __half* Bg = Wh + (size_t)n0 * K_TOTAL;

    const uint32_t s_base = smem_u32(smem);

    // Per-thread loader coordinates (A and B use the same map):
    // chunk i in 0..3: idx = tid + 256*i, row = idx/8, ch = idx%8 (16B units)
    const int ld_row = tid >> 3;        // 0..31  (+32 per chunk)
    const int ld_ch = tid & 7;
    const uint32_t ld_soff = (uint32_t)(ld_row * PAD_H + ld_ch * 8) * 2u;
    const __half* ld_ga = Ag + (size_t)ld_row * K_TOTAL + ld_ch * 8;
    const __half* ld_gb = Bg + (size_t)ld_row * K_TOTAL + ld_ch * 8;

    // Accumulators: 4 m-subtiles x 4 n-subtiles x 4 regs
    float d[4][4][4];
#pragma unroll
    for (int i = 0; i < 4; i++)
#pragma unroll
        for (int j = 0; j < 4; j++) {
            d[i][j][0] = 0.f; d[i][j][1] = 0.f; d[i][j][2] = 0.f; d[i][j][3] = 0.f;
        }

    // One 16B chunk-pair (1 A + 1 B cp.async) for stage `slot`, k-tile kt, chunk i
    auto load_chunk = [&](int kt, int slot, int i) {
        uint32_t sa = s_base + (uint32_t)(slot * STAGE_HALVES) * 2u + ld_soff +
                      (uint32_t)(i * 32 * PAD_H) * 2u;
        cp_async16(sa, ld_ga + (size_t)(i * 32) * K_TOTAL + kt * BK);
        cp_async16(sa + A_ST_HALVES * 2u, ld_gb + (size_t)(i * 32) * K_TOTAL + kt * BK);
    };

    // Prologue: stages 0..1 as bursts (one-time)
#pragma unroll
    for (int s = 0; s < STAGES - 1; s++) {
#pragma unroll
        for (int i = 0; i < 4; i++) load_chunk(s, s, i);
        cp_commit();
    }

    const int Am_base = warp_m * 64;
    const int Bn_base = warp_n * 32;

    // ldmatrix per-lane coordinates.
    const int l8 = lane & 7;
    const int aRow = ((lane >> 3) & 1) * 8 + l8;
    const int aK = (lane >> 4) * 8;
    const int bRow = (lane >> 4) * 8 + l8;
    const int bK = ((lane >> 3) & 1) * 8;

    uint32_t aOff[4], bOff[2];
#pragma unroll
    for (int tm = 0; tm < 4; tm++)
        aOff[tm] = (uint32_t)(((Am_base + tm * 16 + aRow) * PAD_H + aK) * 2);
#pragma unroll
    for (int tp = 0; tp < 2; tp++)
        bOff[tp] = (uint32_t)(((Bn_base + tp * 16 + bRow) * PAD_H + bK) * 2 +
                              A_ST_HALVES * 2);

#pragma unroll 1
    for (int kt = 0; kt < K_ITERS; kt++) {
        cp_wait<STAGES - 2>();
        // Single barrier per kt: stage kt visible + slot (kt+2)%3 drained.
        __syncthreads();

        const int ldk = kt + STAGES - 1;
        const bool do_load = (ldk < K_ITERS);
        const int slot_n = ldk % STAGES;

        const uint32_t st = s_base + (uint32_t)((kt % STAGES) * STAGE_HALVES) * 2u;

#pragma unroll
        for (int kk16 = 0; kk16 < 4; kk16++) {
            const int kk = kk16 * 16;
            uint32_t a[4][4], b[2][4];
            // 1) fragment loads for this kk
#pragma unroll
            for (int tm = 0; tm < 4; tm++)
                ldsm_x4(a[tm][0], a[tm][1], a[tm][2], a[tm][3], st + aOff[tm] + kk * 2);
#pragma unroll
            for (int tp = 0; tp < 2; tp++)
                ldsm_x4(b[tp][0], b[tp][1], b[tp][2], b[tp][3], st + bOff[tp] + kk * 2);
            // 2) next-stage cp.async chunk (issues in the ldsm latency shadow)
            if (do_load) load_chunk(ldk, slot_n, kk16);
            // 3) MMAs
#pragma unroll
            for (int tm = 0; tm < 4; tm++)
#pragma unroll
                for (int tn = 0; tn < 4; tn++)
                    mma_f16(d[tm][tn][0], d[tm][tn][1], d[tm][tn][2], d[tm][tn][3],
                            a[tm][0], a[tm][1], a[tm][2], a[tm][3],
                            b[tn >> 1][2 * (tn & 1)], b[tn >> 1][2 * (tn & 1) + 1]);
        }
        if (do_load) cp_commit();
    }

    // ---- Epilogue: d + bias -> gmem ----
#pragma unroll
    for (int tn = 0; tn < 4; tn++) {
        int col = n0 + Bn_base + tn * 8 + 2 * q;
        float2 bb = *reinterpret_cast<const float2*>(bias + col);
#pragma unroll
        for (int tm = 0; tm < 4; tm++) {
            int row0 = m0 + Am_base + tm * 16 + g;
            float2 v0 = make_float2(d[tm][tn][0] + bb.x, d[tm][tn][1] + bb.y);
            float2 v1 = make_float2(d[tm][tn][2] + bb.x, d[tm][tn][3] + bb.y);
            *reinterpret_cast<float2*>(out + (size_t)row0 * N_TOTAL + col) = v0;
            *reinterpret_cast<float2*>(out + (size_t)(row0 + 8) * N_TOTAL + col) = v1;
        }
    }
}

// ============================================================================
// Host launch
// ============================================================================
extern "C" void kernel_launch(void* const* d_in, const int* in_sizes, int n_in,
                              void* d_out, int out_size) {
    const float* x    = (const float*)d_in[0];  // [4,2048,4096]
    const float* W    = (const float*)d_in[1];  // [4096,4096] (out,in)
    const float* bias = (const float*)d_in[2];  // [4096]
    const float* A    = (const float*)d_in[3];  // [4096,32]
    const float* B    = (const float*)d_in[4];  // [32,4096]
    float* y          = (float*)d_out;          // [4,2048,4096]

    void* xh_ptr = nullptr;
    void* wh_ptr = nullptr;
    cudaGetSymbolAddress(&xh_ptr, g_Xh);
    cudaGetSymbolAddress(&wh_ptr, g_Wh);

    // 1) fused prep: weff blocks first (overlap FMA-bound weff with DRAM-bound conversion)
    prep_kernel<<<WEFF_BLOCKS + CONV_BLOCKS, 256>>>(x, W, A, B);
    // 2) main GEMM + bias epilogue
    cudaFuncSetAttribute((const void*)gemm_kernel,
                         cudaFuncAttributeMaxDynamicSharedMemorySize, SMEM_BYTES);
    gemm_kernel<<<(M_TOTAL / BM) * (N_TOTAL / BN), 256, SMEM_BYTES>>>(
        (const __half*)xh_ptr, (const __half*)wh_ptr, bias, y);
}